// round 7
// baseline (speedup 1.0000x reference)
#include <cuda_runtime.h>
#include <cuda_fp16.h>
#include <stdint.h>
#include <math.h>

#define MAXN 131072
#define PAD  8   // one float per 32B L2 sector for atomic targets

__device__ float  g_h[MAXN];            // x @ W                  [N]
__device__ float  g_dinv[MAXN];         // rsqrt(deg+1)           [N]
__device__ float  g_p[MAXN];            // dinv * h (fp32, k5)    [N]
__device__ __half g_ph[MAXN];           // dinv * h (fp16 gather) [N] -- fits L1
__device__ float  g_deg8[MAXN * PAD];   // sector-padded degree   (zeroed after use)
__device__ float  g_acc8[MAXN * PAD];   // sector-padded scatter  (zeroed after use)

// ---------------------------------------------------------------------------
// K1 (fused): per-warp row dot products (DRAM-bound) + grid-stride degree
// histogram into sector-padded bins (LTS-atomic). Disjoint pipes -> overlap.
// g_deg8 is zero on entry (static zero-init; re-zeroed by k3 every call).
// ---------------------------------------------------------------------------
__global__ void k1_fused(const float* __restrict__ x,
                         const float* __restrict__ W,
                         const int*   __restrict__ dst,
                         int N, int C, int E) {
    int tid  = blockIdx.x * blockDim.x + threadIdx.x;
    int warp = tid >> 5;
    int lane = tid & 31;

    if (warp < N) {
        const float4* xr = reinterpret_cast<const float4*>(x + (size_t)warp * C);
        const float4* w4 = reinterpret_cast<const float4*>(W);

        float4 a0 = xr[lane];
        float4 a1 = xr[lane + 32];
        float4 b0 = __ldg(&w4[lane]);
        float4 b1 = __ldg(&w4[lane + 32]);

        float s = a0.x * b0.x + a0.y * b0.y + a0.z * b0.z + a0.w * b0.w
                + a1.x * b1.x + a1.y * b1.y + a1.z * b1.z + a1.w * b1.w;

        #pragma unroll
        for (int off = 16; off > 0; off >>= 1)
            s += __shfl_xor_sync(0xffffffffu, s, off);

        if (lane == 0) g_h[warp] = s;
    }

    int stride = gridDim.x * blockDim.x;
    for (int i = tid; i < E; i += stride)
        atomicAdd(&g_deg8[(unsigned)dst[i] * PAD], 1.0f);
}

// ---------------------------------------------------------------------------
// K3: dinv = rsqrt(deg+1); p = dinv*h (fp32 + fp16); re-zero deg bins.
// 4 nodes/thread for MLP.
// ---------------------------------------------------------------------------
__global__ void k3_norm(int N) {
    int t = blockIdx.x * blockDim.x + threadIdx.x;
    int base = t * 4;
    #pragma unroll
    for (int k = 0; k < 4; k++) {
        int i = base + k;
        if (i < N) {
            float d = g_deg8[(unsigned)i * PAD];
            g_deg8[(unsigned)i * PAD] = 0.0f;
            float dinv = rsqrtf(d + 1.0f);
            float p = dinv * g_h[i];
            g_dinv[i] = dinv;
            g_p[i]    = p;
            g_ph[i]   = __float2half_rn(p);
        }
    }
}

// ---------------------------------------------------------------------------
// K4: scatter acc[dst] += p[src]; gather from fp16 array (L1-resident),
// atomics into sector-padded fp32 bins.
// ---------------------------------------------------------------------------
__global__ void k4_scatter(const int* __restrict__ src,
                           const int* __restrict__ dst, int E) {
    int i = blockIdx.x * blockDim.x + threadIdx.x;
    int stride = gridDim.x * blockDim.x;
    for (; i < E; i += stride) {
        int s = src[i];
        int d = dst[i];
        float pv = __half2float(g_ph[s]);
        atomicAdd(&g_acc8[(unsigned)d * PAD], pv);
    }
}

// ---------------------------------------------------------------------------
// K5: out = softplus(dinv*(acc+p) + b); re-zero acc bins. 4 nodes/thread.
// (self-loop term dinv^2 h = dinv*p, fp32)
// ---------------------------------------------------------------------------
__global__ void k5_epilogue(float* __restrict__ out,
                            const float* __restrict__ b, int N) {
    int t = blockIdx.x * blockDim.x + threadIdx.x;
    int base = t * 4;
    float bb = b[0];

    float a[4], p[4], q[4];
    #pragma unroll
    for (int k = 0; k < 4; k++) {
        int i = base + k;
        if (i < N) {
            a[k] = g_acc8[(unsigned)i * PAD];
            p[k] = g_p[i];
            q[k] = g_dinv[i];
        }
    }
    #pragma unroll
    for (int k = 0; k < 4; k++) {
        int i = base + k;
        if (i < N) {
            g_acc8[(unsigned)i * PAD] = 0.0f;
            float v = q[k] * (a[k] + p[k]) + bb;
            out[i] = fmaxf(v, 0.0f) + log1pf(expf(-fabsf(v)));
        }
    }
}

extern "C" void kernel_launch(void* const* d_in, const int* in_sizes, int n_in,
                              void* d_out, int out_size) {
    const float* x   = (const float*)d_in[0];
    const int*   ei  = (const int*)d_in[1];   // [2, E], int32
    const float* W   = (const float*)d_in[2];
    const float* b   = (const float*)d_in[3];
    float*       out = (float*)d_out;

    int C = in_sizes[2];            // 256
    int N = in_sizes[0] / C;        // 100000
    int E = in_sizes[1] / 2;        // 3200000

    const int* src = ei;
    const int* dst = ei + E;

    // K1 fused: 512 threads = 16 warps = 16 rows/block; edges grid-stride
    {
        int warps_per_block = 16;
        int blocks = (N + warps_per_block - 1) / warps_per_block;
        k1_fused<<<blocks, 512>>>(x, W, dst, N, C, E);
    }
    // K3: 4 nodes/thread
    {
        int threads = 256;
        int work = (N + 3) / 4;
        int blocks = (work + threads - 1) / threads;
        k3_norm<<<blocks, threads>>>(N);
    }
    // K4: scalar grid-stride, fp16 gather
    {
        int threads = 256;
        int blocks = (E + threads - 1) / threads;
        if (blocks > 65535) blocks = 65535;
        k4_scatter<<<blocks, threads>>>(src, dst, E);
    }
    // K5: 4 nodes/thread
    {
        int threads = 256;
        int work = (N + 3) / 4;
        int blocks = (work + threads - 1) / threads;
        k5_epilogue<<<blocks, threads>>>(out, b, N);
    }
}

// round 8
// speedup vs baseline: 1.1303x; 1.1303x over previous
#include <cuda_runtime.h>
#include <cuda_fp16.h>
#include <stdint.h>
#include <math.h>

#define MAXN 131072
#define PAD  8   // one float per 32B L2 sector for atomic targets

__device__ float  g_h[MAXN];            // x @ W                  [N]
__device__ float  g_dinv[MAXN];         // rsqrt(deg+1)           [N]
__device__ __half g_ph[MAXN];           // fp16 p = dinv*h        [N] (staged to SMEM in k4)
__device__ float  g_deg8[MAXN * PAD];   // sector-padded degree   (zeroed after use)
__device__ float  g_acc8[MAXN * PAD];   // sector-padded scatter  (zeroed after use)

// ---------------------------------------------------------------------------
// K1 (fused): per-warp row dot products (DRAM-bound) + grid-stride degree
// histogram into sector-padded bins (LTS-atomic). Disjoint pipes -> overlap.
// ---------------------------------------------------------------------------
__global__ void k1_fused(const float* __restrict__ x,
                         const float* __restrict__ W,
                         const int*   __restrict__ dst,
                         int N, int C, int E) {
    int tid  = blockIdx.x * blockDim.x + threadIdx.x;
    int warp = tid >> 5;
    int lane = tid & 31;

    if (warp < N) {
        const float4* xr = reinterpret_cast<const float4*>(x + (size_t)warp * C);
        const float4* w4 = reinterpret_cast<const float4*>(W);

        float4 a0 = xr[lane];
        float4 a1 = xr[lane + 32];
        float4 b0 = __ldg(&w4[lane]);
        float4 b1 = __ldg(&w4[lane + 32]);

        float s = a0.x * b0.x + a0.y * b0.y + a0.z * b0.z + a0.w * b0.w
                + a1.x * b1.x + a1.y * b1.y + a1.z * b1.z + a1.w * b1.w;

        #pragma unroll
        for (int off = 16; off > 0; off >>= 1)
            s += __shfl_xor_sync(0xffffffffu, s, off);

        if (lane == 0) g_h[warp] = s;
    }

    int stride = gridDim.x * blockDim.x;
    for (int i = tid; i < E; i += stride)
        atomicAdd(&g_deg8[(unsigned)dst[i] * PAD], 1.0f);
}

// ---------------------------------------------------------------------------
// K3: dinv = rsqrt(deg+1); ph = fp16(dinv*h); re-zero deg bins. 2 nodes/thread.
// ---------------------------------------------------------------------------
__global__ void k3_norm(int N) {
    int t = blockIdx.x * blockDim.x + threadIdx.x;
    int i0 = t * 2, i1 = i0 + 1;
    if (i0 < N) {
        float d0 = g_deg8[(unsigned)i0 * PAD];
        float d1 = (i1 < N) ? g_deg8[(unsigned)i1 * PAD] : 0.0f;
        float h0 = g_h[i0];
        float h1 = (i1 < N) ? g_h[i1] : 0.0f;

        g_deg8[(unsigned)i0 * PAD] = 0.0f;
        float v0 = rsqrtf(d0 + 1.0f);
        g_dinv[i0] = v0;
        g_ph[i0] = __float2half_rn(v0 * h0);

        if (i1 < N) {
            g_deg8[(unsigned)i1 * PAD] = 0.0f;
            float v1 = rsqrtf(d1 + 1.0f);
            g_dinv[i1] = v1;
            g_ph[i1] = __float2half_rn(v1 * h1);
        }
    }
}

// ---------------------------------------------------------------------------
// K4: persistent, one block/SM. Stage fp16 p-vector into SMEM (200KB), then
// grid-stride edges gathering from SMEM; atomics to sector-padded L2 bins.
// Removes ~60MB of random L2 gather sector traffic.
// ---------------------------------------------------------------------------
__global__ void __launch_bounds__(1024, 1)
k4_scatter_smem(const int* __restrict__ src,
                const int* __restrict__ dst, int N, int E) {
    extern __shared__ __half sph[];

    // Stage g_ph -> SMEM as uint4 (16B = 8 halves); MAXN padding makes
    // reading past N (up to the 16B round-up) safe.
    int n16 = (N * 2 + 15) / 16;   // uint4 count
    const uint4* gp4 = reinterpret_cast<const uint4*>(g_ph);
    uint4* sp4 = reinterpret_cast<uint4*>(sph);
    for (int i = threadIdx.x; i < n16; i += blockDim.x)
        sp4[i] = gp4[i];
    __syncthreads();

    int tid = blockIdx.x * blockDim.x + threadIdx.x;
    int stride = gridDim.x * blockDim.x;
    for (int i = tid; i < E; i += stride) {
        int s = src[i];
        int d = dst[i];
        float pv = __half2float(sph[s]);
        atomicAdd(&g_acc8[(unsigned)d * PAD], pv);
    }
}

// fallback (no SMEM staging) if N too large for SMEM
__global__ void k4_scatter_fallback(const int* __restrict__ src,
                                    const int* __restrict__ dst, int E) {
    int i = blockIdx.x * blockDim.x + threadIdx.x;
    int stride = gridDim.x * blockDim.x;
    for (; i < E; i += stride)
        atomicAdd(&g_acc8[(unsigned)dst[i] * PAD], __half2float(g_ph[src[i]]));
}

// ---------------------------------------------------------------------------
// K5: out = softplus(dinv*(acc + dinv*h) + b); re-zero acc bins. 2/thread.
// Self-loop term recomputed in fp32 from g_h (no fp32 p array needed).
// ---------------------------------------------------------------------------
__global__ void k5_epilogue(float* __restrict__ out,
                            const float* __restrict__ b, int N) {
    int t = blockIdx.x * blockDim.x + threadIdx.x;
    int i0 = t * 2, i1 = i0 + 1;
    if (i0 < N) {
        float bb = b[0];
        float a0 = g_acc8[(unsigned)i0 * PAD];
        float a1 = (i1 < N) ? g_acc8[(unsigned)i1 * PAD] : 0.0f;
        float h0 = g_h[i0];
        float h1 = (i1 < N) ? g_h[i1] : 0.0f;
        float q0 = g_dinv[i0];
        float q1 = (i1 < N) ? g_dinv[i1] : 0.0f;

        g_acc8[(unsigned)i0 * PAD] = 0.0f;
        float v0 = q0 * (a0 + q0 * h0) + bb;
        out[i0] = fmaxf(v0, 0.0f) + log1pf(expf(-fabsf(v0)));

        if (i1 < N) {
            g_acc8[(unsigned)i1 * PAD] = 0.0f;
            float v1 = q1 * (a1 + q1 * h1) + bb;
            out[i1] = fmaxf(v1, 0.0f) + log1pf(expf(-fabsf(v1)));
        }
    }
}

extern "C" void kernel_launch(void* const* d_in, const int* in_sizes, int n_in,
                              void* d_out, int out_size) {
    const float* x   = (const float*)d_in[0];
    const int*   ei  = (const int*)d_in[1];   // [2, E], int32
    const float* W   = (const float*)d_in[2];
    const float* b   = (const float*)d_in[3];
    float*       out = (float*)d_out;

    int C = in_sizes[2];            // 256
    int N = in_sizes[0] / C;        // 100000
    int E = in_sizes[1] / 2;        // 3200000

    const int* src = ei;
    const int* dst = ei + E;

    // K1 fused
    {
        int warps_per_block = 16;
        int blocks = (N + warps_per_block - 1) / warps_per_block;
        k1_fused<<<blocks, 512>>>(x, W, dst, N, C, E);
    }
    // K3
    {
        int threads = 256;
        int work = (N + 1) / 2;
        int blocks = (work + threads - 1) / threads;
        k3_norm<<<blocks, threads>>>(N);
    }
    // K4: persistent SMEM-staged scatter (one block per SM)
    {
        int sm_count = 148;
        cudaDeviceGetAttribute(&sm_count, cudaDevAttrMultiProcessorCount, 0);
        size_t smem_bytes = ((size_t)N * 2 + 15) & ~(size_t)15;
        static int smem_attr_set = 0;  // idempotent host-side attr set
        if (!smem_attr_set) {
            cudaFuncSetAttribute(k4_scatter_smem,
                                 cudaFuncAttributeMaxDynamicSharedMemorySize,
                                 227 * 1024);
            smem_attr_set = 1;
        }
        if (smem_bytes <= 227 * 1024) {
            k4_scatter_smem<<<sm_count, 1024, smem_bytes>>>(src, dst, N, E);
        } else {
            int threads = 256;
            int blocks = (E + threads - 1) / threads;
            if (blocks > 65535) blocks = 65535;
            k4_scatter_fallback<<<blocks, threads>>>(src, dst, E);
        }
    }
    // K5
    {
        int threads = 256;
        int work = (N + 1) / 2;
        int blocks = (work + threads - 1) / threads;
        k5_epilogue<<<blocks, threads>>>(out, b, N);
    }
}